// round 8
// baseline (speedup 1.0000x reference)
#include <cuda_runtime.h>
#include <cstdint>

#define NB 64
#define NN 1024
#define DD 128
#define KK 6
#define NBINS 64
#define BINW (1.0f / 64.0f)
#define GEMM_BLOCKS (32 * KK)   // 192

// Scratch (device globals: no allocation allowed)
__device__ float g_G[NN * KK * DD];            // 3 MB  : G[j][k][d]
__device__ int   g_nbr[NB * NN * KK];          // 1.5 MB: neighbor indices
__device__ float g_part[(NB * NN / 8) * DD];   // 4 MB  : per-gather-block mean partials

// ---------------------------------------------------------------------------
// KA: fused.  blocks [0,192): GEMM  G[j,k,d] = sum_dp F2[0,j,dp]*Wnb[d,k*128+dp]
//             blocks [192,256): exact kNN for batch (bid-192), 1 row/thread.
// 1024 threads. Shared memory overlaid via byte arena (max 32.9 KB).
// ---------------------------------------------------------------------------
__global__ __launch_bounds__(1024, 1)
void k_fused_pre(const float* __restrict__ loc,
                 const float* __restrict__ W2d,
                 const float* __restrict__ b2d,
                 const float* __restrict__ Wnb) {
    __shared__ __align__(16) unsigned char sraw[33024];
    const int tid = threadIdx.x;

    if (blockIdx.x < GEMM_BLOCKS) {
        // ================= GEMM path =================
        float (*F2s)[128] = (float(*)[128])sraw;              // 16384 B
        float (*Ws)[129]  = (float(*)[129])(sraw + 16384);    // 16512 B

        const int bx = blockIdx.x;
        const int jt = bx / KK;
        const int k  = bx - jt * KK;
        const int j0 = jt * 32;

        for (int idx = tid; idx < 32 * 128; idx += 1024) {
            int jr = idx >> 7, dd = idx & 127;
            int jg = j0 + jr;
            float x = loc[jg * 2 + 0], y = loc[jg * 2 + 1];
            F2s[jr][dd] = fmaf(y, W2d[dd * 2 + 1], fmaf(x, W2d[dd * 2 + 0], b2d[dd]));
        }

        const int td = tid & 63;      // d and d+64
        const int tj = tid >> 6;      // 0..15 -> rows 2tj, 2tj+1
        const int ldp = tid & 31;     // staging lane -> dp (coalesced)
        const int ld0 = tid >> 5;     // staging warp  -> d

        float a00 = 0.f, a01 = 0.f, a10 = 0.f, a11 = 0.f;

        for (int dpc = 0; dpc < 128; dpc += 32) {
            __syncthreads();
            for (int dd = ld0; dd < 128; dd += 32)
                Ws[ldp][dd] = Wnb[dd * (KK * DD) + k * DD + dpc + ldp];
            __syncthreads();

#pragma unroll
            for (int dp = 0; dp < 32; dp++) {
                float w0 = Ws[dp][td];
                float w1 = Ws[dp][td + 64];
                float f0 = F2s[2 * tj + 0][dpc + dp];
                float f1 = F2s[2 * tj + 1][dpc + dp];
                a00 = fmaf(f0, w0, a00);
                a01 = fmaf(f0, w1, a01);
                a10 = fmaf(f1, w0, a10);
                a11 = fmaf(f1, w1, a11);
            }
        }

        size_t r0 = ((size_t)((j0 + 2 * tj + 0) * KK + k)) * DD;
        size_t r1 = ((size_t)((j0 + 2 * tj + 1) * KK + k)) * DD;
        g_G[r0 + td] = a00;  g_G[r0 + td + 64] = a01;
        g_G[r1 + td] = a10;  g_G[r1 + td + 64] = a11;
    } else {
        // ================= kNN path (one batch per block) =================
        float2* lx = (float2*)sraw;                       //  8192 B
        float2* ps = (float2*)(sraw + 8192);              //  8192 B
        short*  js = (short*)(sraw + 16384);              //  2048 B
        unsigned char* binOf = sraw + 18432;              //  1024 B
        int* bin_cnt   = (int*)(sraw + 19456);            //   256 B
        int* bin_start = (int*)(sraw + 19712);
        int* bin_fill  = (int*)(sraw + 19968);

        const int b = blockIdx.x - GEMM_BLOCKS;

        if (tid < NBINS) { bin_cnt[tid] = 0; bin_fill[tid] = 0; }
        __syncthreads();

        const float2* locb = (const float2*)(loc + (size_t)b * NN * 2);
        {
            float2 p = locb[tid];
            lx[tid] = p;
            int bn = (int)(p.x * 64.0f);
            bn = bn < 0 ? 0 : (bn > 63 ? 63 : bn);
            binOf[tid] = (unsigned char)bn;
            atomicAdd(&bin_cnt[bn], 1);
        }
        __syncthreads();

        // Exclusive prefix over 64 bins by warp 0.
        if (tid < 32) {
            int c0 = bin_cnt[tid];
            int c1 = bin_cnt[tid + 32];
            int s0 = c0, s1 = c1;
#pragma unroll
            for (int off = 1; off < 32; off <<= 1) {
                int v0 = __shfl_up_sync(0xffffffffu, s0, off);
                int v1 = __shfl_up_sync(0xffffffffu, s1, off);
                if (tid >= off) { s0 += v0; s1 += v1; }
            }
            int tot0 = __shfl_sync(0xffffffffu, s0, 31);
            bin_start[tid]      = s0 - c0;
            bin_start[tid + 32] = s1 + tot0 - c1;
        }
        __syncthreads();

        // Deterministic scatter by warp 0: j-order ranks within each bin.
        if (tid < 32) {
            const unsigned lmask = (1u << tid) - 1u;
            for (int g = 0; g < 32; g++) {
                int j = g * 32 + tid;
                int bn = binOf[j];
                unsigned mask = __match_any_sync(0xffffffffu, bn);
                int leader = __ffs(mask) - 1;
                int lower = __popc(mask & lmask);
                int base = 0;
                if (tid == leader) base = atomicAdd(&bin_fill[bn], __popc(mask));
                base = __shfl_sync(0xffffffffu, base, leader);
                int pos = bin_start[bn] + base + lower;
                ps[pos] = lx[j];
                js[pos] = (short)j;
            }
        }
        __syncthreads();

        // Per-row outward scan; key = (d2_bits << 32) | j (stable tie-break).
        const int n = tid;
        const float xi = lx[n].x, yi = lx[n].y;
        const unsigned long long KINIT =
            (((unsigned long long)0x7f800000u) << 32) | 0xffffffffull;
        unsigned long long k0 = KINIT, k1 = KINIT, k2 = KINIT,
                           k3 = KINIT, k4 = KINIT, k5 = KINIT;

#define PROC_BIN(c)                                                          \
        {                                                                    \
            int s_ = bin_start[c];                                           \
            int e_ = s_ + bin_cnt[c];                                        \
            for (int i_ = s_; i_ < e_; i_++) {                               \
                float2 p_ = ps[i_];                                          \
                float dx_ = p_.x - xi;                                       \
                float dy_ = p_.y - yi;                                       \
                float d2_ = fmaf(dx_, dx_, dy_ * dy_);                       \
                unsigned long long key_ =                                    \
                    (((unsigned long long)__float_as_uint(d2_)) << 32) |     \
                    (unsigned)(unsigned short)js[i_];                        \
                if (key_ < k5) {                                             \
                    bool c4 = key_ < k4, c3 = key_ < k3, c2 = key_ < k2,     \
                         c1_ = key_ < k1, c0_ = key_ < k0;                   \
                    k5 = c4 ? k4 : key_;                                     \
                    k4 = c4 ? (c3 ? k3 : key_) : k4;                         \
                    k3 = c3 ? (c2 ? k2 : key_) : k3;                         \
                    k2 = c2 ? (c1_ ? k1 : key_) : k2;                        \
                    k1 = c1_ ? (c0_ ? k0 : key_) : k1;                       \
                    k0 = c0_ ? key_ : k0;                                    \
                }                                                            \
            }                                                                \
        }

        int b0 = (int)(xi * 64.0f);
        b0 = b0 < 0 ? 0 : (b0 > 63 ? 63 : b0);
        PROC_BIN(b0);
        int cr = b0 + 1, cl = b0 - 1;
        bool rA = cr < NBINS, lA = cl >= 0;
        while (rA || lA) {
            if (rA) {
                float t = __uint_as_float((unsigned)(k5 >> 32));
                float dmin = cr * BINW - xi;
                if (dmin * dmin > t) rA = false;
                else { PROC_BIN(cr); cr++; rA = cr < NBINS; }
            }
            if (lA) {
                float t = __uint_as_float((unsigned)(k5 >> 32));
                float dmin = xi - (cl + 1) * BINW;
                if (dmin * dmin > t) lA = false;
                else { PROC_BIN(cl); cl--; lA = cl >= 0; }
            }
        }
#undef PROC_BIN

        int obase = (b * NN + n) * KK;
        g_nbr[obase + 0] = (int)(k0 & 0xffffffffu);
        g_nbr[obase + 1] = (int)(k1 & 0xffffffffu);
        g_nbr[obase + 2] = (int)(k2 & 0xffffffffu);
        g_nbr[obase + 3] = (int)(k3 & 0xffffffffu);
        g_nbr[obase + 4] = (int)(k4 & 0xffffffffu);
        g_nbr[obase + 5] = (int)(k5 & 0xffffffffu);
    }
}

// ---------------------------------------------------------------------------
// KB: gather G rows + bnb + F3 + leaky-relu; write h[b,n+1,:]; block-level
// mean partial to g_part. grid = 8192 (8 rows, 1 warp/row), 256 threads.
// ---------------------------------------------------------------------------
__global__ void k_gather(const float* __restrict__ loc,
                         const float* __restrict__ deadline,
                         const float* __restrict__ W3d,
                         const float* __restrict__ b3d,
                         const float* __restrict__ bnb,
                         float* __restrict__ h) {
    __shared__ float red[8][128];
    const int tid = threadIdx.x;
    const int w = tid >> 5, l = tid & 31;
    const int row = blockIdx.x * 8 + w;          // 0..65535
    const int b = row >> 10, n = row & 1023;

    float w3[4][3], b3v[4];
#pragma unroll
    for (int q = 0; q < 4; q++) {
        int d = 4 * l + q;
        w3[q][0] = W3d[d * 3 + 0];
        w3[q][1] = W3d[d * 3 + 1];
        w3[q][2] = W3d[d * 3 + 2];
        b3v[q] = b3d[d];
    }
    float4 bnv = ((const float4*)bnb)[l];
    float a[4] = {bnv.x, bnv.y, bnv.z, bnv.w};

    const int* nb = g_nbr + (size_t)row * KK;
#pragma unroll
    for (int k = 0; k < KK; k++) {
        int j = __ldg(nb + k);
        float4 g = ((const float4*)(g_G + (size_t)(j * KK + k) * DD))[l];
        a[0] += g.x; a[1] += g.y; a[2] += g.z; a[3] += g.w;
    }

    float xn = loc[(size_t)row * 2 + 0];
    float yn = loc[(size_t)row * 2 + 1];
    float tn = deadline[row];

    float4 o;
    float* op = (float*)&o;
#pragma unroll
    for (int q = 0; q < 4; q++) {
        float f3 = fmaf(tn, w3[q][2], fmaf(yn, w3[q][1], fmaf(xn, w3[q][0], b3v[q])));
        float v = a[q] + f3;
        op[q] = (v >= 0.f) ? v : 0.01f * v;
    }
    ((float4*)(h + ((size_t)(b * (NN + 1) + n + 1)) * DD))[l] = o;

    // Mean partial over this block's 8 rows (deterministic order).
    ((float4*)red[w])[l] = o;
    __syncthreads();
    if (tid < 128) {
        float s = 0.f;
#pragma unroll
        for (int q = 0; q < 8; q++) s += red[q][tid];
        g_part[(size_t)blockIdx.x * DD + tid] = s;
    }
}

// ---------------------------------------------------------------------------
// KC: depot row + mean combine. grid = 64, 1024 threads.
// 8 groups x 16 partial-blocks each, coalesced; smem tree combine.
// ---------------------------------------------------------------------------
__global__ void k_final(const float* __restrict__ depot,
                        const float* __restrict__ Wdep,
                        const float* __restrict__ bdep,
                        float* __restrict__ h,
                        float* __restrict__ mean_out) {
    __shared__ float red[8][128];
    const int b = blockIdx.x;
    const int tid = threadIdx.x;
    const int d = tid & 127, g = tid >> 7;     // 8 groups of 128

    float s = 0.f;
    const float* pp = g_part + (size_t)b * 128 * DD;
#pragma unroll
    for (int q = 0; q < 16; q++) s += pp[(size_t)(g * 16 + q) * DD + d];

    if (g == 0) {
        float dep = fmaf(depot[b * 2 + 1], Wdep[d * 2 + 1],
                         fmaf(depot[b * 2 + 0], Wdep[d * 2 + 0], bdep[d]));
        dep = (dep >= 0.f) ? dep : 0.01f * dep;
        h[(size_t)b * (NN + 1) * DD + d] = dep;
        s += dep;
    }
    red[g][d] = s;
    __syncthreads();
    if (g == 0) {
        float t = 0.f;
#pragma unroll
        for (int q = 0; q < 8; q++) t += red[q][d];
        mean_out[b * DD + d] = t / 1025.0f;
    }
}

// ---------------------------------------------------------------------------
extern "C" void kernel_launch(void* const* d_in, const int* in_sizes, int n_in,
                              void* d_out, int out_size) {
    const float* loc      = (const float*)d_in[0];
    const float* deadline = (const float*)d_in[1];
    const float* depot    = (const float*)d_in[2];
    const float* W3d      = (const float*)d_in[3];
    const float* b3d      = (const float*)d_in[4];
    const float* W2d      = (const float*)d_in[5];
    const float* b2d      = (const float*)d_in[6];
    const float* Wnb      = (const float*)d_in[7];
    const float* bnb      = (const float*)d_in[8];
    const float* Wdep     = (const float*)d_in[9];
    const float* bdep     = (const float*)d_in[10];

    float* h = (float*)d_out;
    float* mean_out = h + (size_t)NB * (NN + 1) * DD;

    k_fused_pre<<<GEMM_BLOCKS + NB, 1024>>>(loc, W2d, b2d, Wnb);
    k_gather<<<NB * NN / 8, 256>>>(loc, deadline, W3d, b3d, bnb, h);
    k_final<<<NB, 1024>>>(depot, Wdep, bdep, h, mean_out);
}

// round 10
// speedup vs baseline: 1.2023x; 1.2023x over previous
#include <cuda_runtime.h>
#include <cstdint>

#define NB 64
#define NN 1024
#define DD 128
#define KK 6
#define NCX 16
#define NCELL 256
#define CW (1.0f / 16.0f)

// Scratch (device globals: no allocation allowed)
__device__ float g_G[NN * KK * DD];            // 3 MB  : G[j][k][d]
__device__ int   g_nbr[NB * NN * KK];          // 1.5 MB: neighbor indices
__device__ float g_part[(NB * NN / 8) * DD];   // 4 MB  : per-gather-block mean partials

// ---------------------------------------------------------------------------
// K1: G[j,k,d] = sum_dp F2[0,j,dp] * Wnb[d, k*128+dp]
// grid = 192 blocks, 1024 threads, 2j x 2d register tile.
// ---------------------------------------------------------------------------
__global__ void k_precompute(const float* __restrict__ loc,
                             const float* __restrict__ W2d,
                             const float* __restrict__ b2d,
                             const float* __restrict__ Wnb) {
    __shared__ float F2s[32][128];
    __shared__ float Ws[32][129];

    const int bx = blockIdx.x;
    const int jt = bx / KK;
    const int k  = bx - jt * KK;
    const int j0 = jt * 32;
    const int tid = threadIdx.x;

    for (int idx = tid; idx < 32 * 128; idx += 1024) {
        int jr = idx >> 7, dd = idx & 127;
        int jg = j0 + jr;
        float x = loc[jg * 2 + 0], y = loc[jg * 2 + 1];
        F2s[jr][dd] = fmaf(y, W2d[dd * 2 + 1], fmaf(x, W2d[dd * 2 + 0], b2d[dd]));
    }

    const int td = tid & 63;
    const int tj = tid >> 6;
    const int ldp = tid & 31;
    const int ld0 = tid >> 5;

    float a00 = 0.f, a01 = 0.f, a10 = 0.f, a11 = 0.f;

    for (int dpc = 0; dpc < 128; dpc += 32) {
        __syncthreads();
        for (int dd = ld0; dd < 128; dd += 32)
            Ws[ldp][dd] = Wnb[dd * (KK * DD) + k * DD + dpc + ldp];
        __syncthreads();

#pragma unroll
        for (int dp = 0; dp < 32; dp++) {
            float w0 = Ws[dp][td];
            float w1 = Ws[dp][td + 64];
            float f0 = F2s[2 * tj + 0][dpc + dp];
            float f1 = F2s[2 * tj + 1][dpc + dp];
            a00 = fmaf(f0, w0, a00);
            a01 = fmaf(f0, w1, a01);
            a10 = fmaf(f1, w0, a10);
            a11 = fmaf(f1, w1, a11);
        }
    }

    size_t r0 = ((size_t)((j0 + 2 * tj + 0) * KK + k)) * DD;
    size_t r1 = ((size_t)((j0 + 2 * tj + 1) * KK + k)) * DD;
    g_G[r0 + td] = a00;  g_G[r0 + td + 64] = a01;
    g_G[r1 + td] = a10;  g_G[r1 + td + 64] = a11;
}

// ---------------------------------------------------------------------------
// K2: exact kNN via 16x16 cells, rows processed in CELL-SORTED order so
// warps are spatially coherent. grid = 256 (4/batch), 256 threads.
// Key = (d2_bits << 32) | j  -> exact top-k with lower-index tie-break.
// ---------------------------------------------------------------------------
__global__ void k_knn(const float* __restrict__ loc) {
    __shared__ float2 lx[NN];
    __shared__ float2 ps[NN];
    __shared__ short  js[NN];
    __shared__ unsigned char cellOf[NN];
    __shared__ int cnt[NCELL];
    __shared__ int cstart[NCELL];
    __shared__ int cfill[NCELL];

    const int b = blockIdx.x >> 2;
    const int rowbase = (blockIdx.x & 3) << 8;
    const int tid = threadIdx.x;

    if (tid < NCELL) { cnt[tid] = 0; cfill[tid] = 0; }
    __syncthreads();

    const float2* locb = (const float2*)(loc + (size_t)b * NN * 2);
    for (int j = tid; j < NN; j += 256) {
        float2 p = locb[j];
        lx[j] = p;
        int cx = (int)(p.x * 16.0f); cx = cx < 0 ? 0 : (cx > 15 ? 15 : cx);
        int cy = (int)(p.y * 16.0f); cy = cy < 0 ? 0 : (cy > 15 ? 15 : cy);
        int c = cy * NCX + cx;
        cellOf[j] = (unsigned char)c;
        atomicAdd(&cnt[c], 1);
    }
    __syncthreads();

    // Exclusive prefix over 256 cells by warp 0 (8 cells/lane).
    if (tid < 32) {
        int base = tid * 8;
        int c8[8]; int T = 0;
#pragma unroll
        for (int i = 0; i < 8; i++) { c8[i] = cnt[base + i]; T += c8[i]; }
        int incl = T;
#pragma unroll
        for (int off = 1; off < 32; off <<= 1) {
            int v = __shfl_up_sync(0xffffffffu, incl, off);
            if (tid >= off) incl += v;
        }
        int run = incl - T;
#pragma unroll
        for (int i = 0; i < 8; i++) { cstart[base + i] = run; run += c8[i]; }
    }
    __syncthreads();

    // Deterministic scatter by warp 0: j-ascending within each cell.
    if (tid < 32) {
        const unsigned lmask = (1u << tid) - 1u;
        for (int g = 0; g < 32; g++) {
            int j = g * 32 + tid;
            int c = cellOf[j];
            unsigned mask = __match_any_sync(0xffffffffu, c);
            int leader = __ffs(mask) - 1;
            int lower = __popc(mask & lmask);
            int base = 0;
            if (tid == leader) base = atomicAdd(&cfill[c], __popc(mask));
            base = __shfl_sync(0xffffffffu, base, leader);
            int pos = cstart[c] + base + lower;
            ps[pos] = lx[j];
            js[pos] = (short)j;
        }
    }
    __syncthreads();

    // Each thread handles SORTED position rowbase+tid (spatially coherent warps).
    const int sp = rowbase + tid;
    const float2 q = ps[sp];
    const int n = js[sp];
    const float qx = q.x, qy = q.y;

    const unsigned long long KINIT =
        (((unsigned long long)0x7f800000u) << 32) | 0xffffffffull;
    unsigned long long k0 = KINIT, k1 = KINIT, k2 = KINIT,
                       k3 = KINIT, k4 = KINIT, k5 = KINIT;

#define PROC_CELL(c)                                                         \
    {                                                                        \
        int s_ = cstart[c];                                                  \
        int e_ = s_ + cnt[c];                                                \
        for (int i_ = s_; i_ < e_; i_++) {                                   \
            float2 p_ = ps[i_];                                              \
            float dx_ = p_.x - qx;                                           \
            float dy_ = p_.y - qy;                                           \
            float d2_ = fmaf(dx_, dx_, dy_ * dy_);                           \
            unsigned long long key_ =                                        \
                (((unsigned long long)__float_as_uint(d2_)) << 32) |         \
                (unsigned)(unsigned short)js[i_];                            \
            if (key_ < k5) {                                                 \
                bool c4 = key_ < k4, c3 = key_ < k3, c2 = key_ < k2,         \
                     c1_ = key_ < k1, c0_ = key_ < k0;                       \
                k5 = c4 ? k4 : key_;                                         \
                k4 = c4 ? (c3 ? k3 : key_) : k4;                             \
                k3 = c3 ? (c2 ? k2 : key_) : k3;                             \
                k2 = c2 ? (c1_ ? k1 : key_) : k2;                            \
                k1 = c1_ ? (c0_ ? k0 : key_) : k1;                           \
                k0 = c0_ ? key_ : k0;                                        \
            }                                                                \
        }                                                                    \
    }

#define CHECK_PROC(ci, cj)                                                   \
    {                                                                        \
        float dxm_ = fmaxf(0.f, fmaxf((ci) * CW - qx, qx - ((ci) + 1) * CW));\
        float dym_ = fmaxf(0.f, fmaxf((cj) * CW - qy, qy - ((cj) + 1) * CW));\
        float bd_ = __uint_as_float((unsigned)(k5 >> 32));                   \
        if (fmaf(dxm_, dxm_, dym_ * dym_) <= bd_) PROC_CELL((cj) * NCX + (ci));\
    }

    int cx = (int)(qx * 16.0f); cx = cx < 0 ? 0 : (cx > 15 ? 15 : cx);
    int cy = (int)(qy * 16.0f); cy = cy < 0 ? 0 : (cy > 15 ? 15 : cy);

    PROC_CELL(cy * NCX + cx);

    for (int r = 1; r < 16; r++) {
        float dmin = (r - 1) * CW;
        float bd5 = __uint_as_float((unsigned)(k5 >> 32));
        if (dmin * dmin > bd5) break;

        int ci0 = cx - r < 0 ? 0 : cx - r;
        int ci1 = cx + r > 15 ? 15 : cx + r;
        if (cy - r >= 0) {
            int cj = cy - r;
            for (int ci = ci0; ci <= ci1; ci++) CHECK_PROC(ci, cj);
        }
        if (cy + r <= 15) {
            int cj = cy + r;
            for (int ci = ci0; ci <= ci1; ci++) CHECK_PROC(ci, cj);
        }
        int cj0 = cy - r + 1 < 0 ? 0 : cy - r + 1;
        int cj1 = cy + r - 1 > 15 ? 15 : cy + r - 1;
        if (cx - r >= 0) {
            int ci = cx - r;
            for (int cj = cj0; cj <= cj1; cj++) CHECK_PROC(ci, cj);
        }
        if (cx + r <= 15) {
            int ci = cx + r;
            for (int cj = cj0; cj <= cj1; cj++) CHECK_PROC(ci, cj);
        }
    }
#undef CHECK_PROC
#undef PROC_CELL

    int obase = (b * NN + n) * KK;
    g_nbr[obase + 0] = (int)(k0 & 0xffffffffu);
    g_nbr[obase + 1] = (int)(k1 & 0xffffffffu);
    g_nbr[obase + 2] = (int)(k2 & 0xffffffffu);
    g_nbr[obase + 3] = (int)(k3 & 0xffffffffu);
    g_nbr[obase + 4] = (int)(k4 & 0xffffffffu);
    g_nbr[obase + 5] = (int)(k5 & 0xffffffffu);
}

// ---------------------------------------------------------------------------
// K3: gather G rows + bnb + F3 + leaky-relu; write h[b,n+1,:]; block-level
// mean partial to g_part. grid = 8192 (8 rows, 1 warp/row), 256 threads.
// ---------------------------------------------------------------------------
__global__ void k_gather(const float* __restrict__ loc,
                         const float* __restrict__ deadline,
                         const float* __restrict__ W3d,
                         const float* __restrict__ b3d,
                         const float* __restrict__ bnb,
                         float* __restrict__ h) {
    __shared__ float red[8][128];
    const int tid = threadIdx.x;
    const int w = tid >> 5, l = tid & 31;
    const int row = blockIdx.x * 8 + w;
    const int b = row >> 10, n = row & 1023;

    float w3[4][3], b3v[4];
#pragma unroll
    for (int q = 0; q < 4; q++) {
        int d = 4 * l + q;
        w3[q][0] = W3d[d * 3 + 0];
        w3[q][1] = W3d[d * 3 + 1];
        w3[q][2] = W3d[d * 3 + 2];
        b3v[q] = b3d[d];
    }
    float4 bnv = ((const float4*)bnb)[l];
    float a[4] = {bnv.x, bnv.y, bnv.z, bnv.w};

    const int* nb = g_nbr + (size_t)row * KK;
#pragma unroll
    for (int k = 0; k < KK; k++) {
        int j = __ldg(nb + k);
        float4 g = ((const float4*)(g_G + (size_t)(j * KK + k) * DD))[l];
        a[0] += g.x; a[1] += g.y; a[2] += g.z; a[3] += g.w;
    }

    float xn = loc[(size_t)row * 2 + 0];
    float yn = loc[(size_t)row * 2 + 1];
    float tn = deadline[row];

    float4 o;
    float* op = (float*)&o;
#pragma unroll
    for (int q = 0; q < 4; q++) {
        float f3 = fmaf(tn, w3[q][2], fmaf(yn, w3[q][1], fmaf(xn, w3[q][0], b3v[q])));
        float v = a[q] + f3;
        op[q] = (v >= 0.f) ? v : 0.01f * v;
    }
    ((float4*)(h + ((size_t)(b * (NN + 1) + n + 1)) * DD))[l] = o;

    ((float4*)red[w])[l] = o;
    __syncthreads();
    if (tid < 128) {
        float s = 0.f;
#pragma unroll
        for (int q = 0; q < 8; q++) s += red[q][tid];
        g_part[(size_t)blockIdx.x * DD + tid] = s;
    }
}

// ---------------------------------------------------------------------------
// K4: depot row + mean combine. grid = 64, 1024 threads.
// ---------------------------------------------------------------------------
__global__ void k_final(const float* __restrict__ depot,
                        const float* __restrict__ Wdep,
                        const float* __restrict__ bdep,
                        float* __restrict__ h,
                        float* __restrict__ mean_out) {
    __shared__ float red[8][128];
    const int b = blockIdx.x;
    const int tid = threadIdx.x;
    const int d = tid & 127, g = tid >> 7;

    float s = 0.f;
    const float* pp = g_part + (size_t)b * 128 * DD;
#pragma unroll
    for (int q = 0; q < 16; q++) s += pp[(size_t)(g * 16 + q) * DD + d];

    if (g == 0) {
        float dep = fmaf(depot[b * 2 + 1], Wdep[d * 2 + 1],
                         fmaf(depot[b * 2 + 0], Wdep[d * 2 + 0], bdep[d]));
        dep = (dep >= 0.f) ? dep : 0.01f * dep;
        h[(size_t)b * (NN + 1) * DD + d] = dep;
        s += dep;
    }
    red[g][d] = s;
    __syncthreads();
    if (g == 0) {
        float t = 0.f;
#pragma unroll
        for (int q = 0; q < 8; q++) t += red[q][d];
        mean_out[b * DD + d] = t / 1025.0f;
    }
}

// ---------------------------------------------------------------------------
extern "C" void kernel_launch(void* const* d_in, const int* in_sizes, int n_in,
                              void* d_out, int out_size) {
    const float* loc      = (const float*)d_in[0];
    const float* deadline = (const float*)d_in[1];
    const float* depot    = (const float*)d_in[2];
    const float* W3d      = (const float*)d_in[3];
    const float* b3d      = (const float*)d_in[4];
    const float* W2d      = (const float*)d_in[5];
    const float* b2d      = (const float*)d_in[6];
    const float* Wnb      = (const float*)d_in[7];
    const float* bnb      = (const float*)d_in[8];
    const float* Wdep     = (const float*)d_in[9];
    const float* bdep     = (const float*)d_in[10];

    float* h = (float*)d_out;
    float* mean_out = h + (size_t)NB * (NN + 1) * DD;

    k_precompute<<<32 * KK, 1024>>>(loc, W2d, b2d, Wnb);
    k_knn<<<NB * 4, 256>>>(loc);
    k_gather<<<NB * NN / 8, 256>>>(loc, deadline, W3d, b3d, bnb, h);
    k_final<<<NB, 1024>>>(depot, Wdep, bdep, h, mean_out);
}

// round 12
// speedup vs baseline: 1.5015x; 1.2488x over previous
#include <cuda_runtime.h>
#include <cstdint>

#define NB 64
#define NN 1024
#define DD 128
#define KK 6
#define NCX 16
#define NCELL 256
#define CW (1.0f / 16.0f)
#define KNN_BLOCKS (NB * 4)   // 256

// Scratch (device globals: no allocation allowed)
__device__ float g_G[NN * KK * DD];            // 3 MB  : G[j][k][d]
__device__ int   g_nbr[NB * NN * KK];          // 1.5 MB: neighbor indices
__device__ float g_P[KK * DD];
__device__ float g_Q[KK * DD];
__device__ float g_R[KK * DD];
__device__ float g_part[(NB * NN / 8) * DD];   // 4 MB : per-gather-block partials

// ---------------------------------------------------------------------------
// K1 (fused): blocks [0,256): exact kNN (16x16 cells, cell-sorted rows,
//             SERIAL proven scatter);  blocks [256,262): weight collapse.
// ---------------------------------------------------------------------------
__global__ void k_knn_weights(const float* __restrict__ loc,
                              const float* __restrict__ W2d,
                              const float* __restrict__ b2d,
                              const float* __restrict__ Wnb) {
    const int tid = threadIdx.x;

    if (blockIdx.x >= KNN_BLOCKS) {
        // ============ weights path: one k per block ============
        __shared__ float w0s[128], w1s[128], bs[128];
        __shared__ float pa[128], qa[128], ra[128];
        const int k = blockIdx.x - KNN_BLOCKS;

        if (tid < 128) {
            w0s[tid] = W2d[tid * 2 + 0];
            w1s[tid] = W2d[tid * 2 + 1];
            bs[tid]  = b2d[tid];
        }
        __syncthreads();

        const int d = tid >> 1, half = tid & 1;
        float p = 0.f, q = 0.f, r = 0.f;
        const float* wrow = Wnb + d * (KK * DD) + k * DD + half * 64;
#pragma unroll 8
        for (int i = 0; i < 64; i++) {
            float wv = __ldg(wrow + i);
            int dd = half * 64 + i;
            p = fmaf(w0s[dd], wv, p);
            q = fmaf(w1s[dd], wv, q);
            r = fmaf(bs[dd],  wv, r);
        }
        if (half) { pa[d] = p; qa[d] = q; ra[d] = r; }
        __syncthreads();
        if (!half) {
            g_P[k * DD + d] = p + pa[d];
            g_Q[k * DD + d] = q + qa[d];
            g_R[k * DD + d] = r + ra[d];
        }
        return;
    }

    // ============ kNN path (R10-proven) ============
    __shared__ float2 lx[NN];
    __shared__ float2 ps[NN];
    __shared__ short  js[NN];
    __shared__ unsigned char cellOf[NN];
    __shared__ int cnt[NCELL];
    __shared__ int cstart[NCELL];
    __shared__ int cfill[NCELL];

    const int b = blockIdx.x >> 2;
    const int rowbase = (blockIdx.x & 3) << 8;

    if (tid < NCELL) { cnt[tid] = 0; cfill[tid] = 0; }
    __syncthreads();

    const float2* locb = (const float2*)(loc + (size_t)b * NN * 2);
    for (int j = tid; j < NN; j += 256) {
        float2 p = locb[j];
        lx[j] = p;
        int cx = (int)(p.x * 16.0f); cx = cx < 0 ? 0 : (cx > 15 ? 15 : cx);
        int cy = (int)(p.y * 16.0f); cy = cy < 0 ? 0 : (cy > 15 ? 15 : cy);
        int c = cy * NCX + cx;
        cellOf[j] = (unsigned char)c;
        atomicAdd(&cnt[c], 1);
    }
    __syncthreads();

    // Exclusive prefix over 256 cells by warp 0 (8 cells/lane).
    if (tid < 32) {
        int base = tid * 8;
        int c8[8]; int T = 0;
#pragma unroll
        for (int i = 0; i < 8; i++) { c8[i] = cnt[base + i]; T += c8[i]; }
        int incl = T;
#pragma unroll
        for (int off = 1; off < 32; off <<= 1) {
            int v = __shfl_up_sync(0xffffffffu, incl, off);
            if (tid >= off) incl += v;
        }
        int run = incl - T;
#pragma unroll
        for (int i = 0; i < 8; i++) { cstart[base + i] = run; run += c8[i]; }
    }
    __syncthreads();

    // Serial (proven) scatter by warp 0: j-ascending within each cell.
    if (tid < 32) {
        const unsigned lmask = (1u << tid) - 1u;
        for (int g = 0; g < 32; g++) {
            int j = g * 32 + tid;
            int c = cellOf[j];
            unsigned mask = __match_any_sync(0xffffffffu, c);
            int leader = __ffs(mask) - 1;
            int lower = __popc(mask & lmask);
            int base = 0;
            if (tid == leader) base = atomicAdd(&cfill[c], __popc(mask));
            base = __shfl_sync(0xffffffffu, base, leader);
            int pos = cstart[c] + base + lower;
            ps[pos] = lx[j];
            js[pos] = (short)j;
        }
    }
    __syncthreads();

    const int sp = rowbase + tid;
    const float2 qpt = ps[sp];
    const int n = js[sp];
    const float qx = qpt.x, qy = qpt.y;

    const unsigned long long KINIT =
        (((unsigned long long)0x7f800000u) << 32) | 0xffffffffull;
    unsigned long long k0 = KINIT, k1 = KINIT, k2 = KINIT,
                       k3 = KINIT, k4 = KINIT, k5 = KINIT;

#define PROC_CELL(c)                                                         \
    {                                                                        \
        int s_ = cstart[c];                                                  \
        int e_ = s_ + cnt[c];                                                \
        for (int i_ = s_; i_ < e_; i_++) {                                   \
            float2 p_ = ps[i_];                                              \
            float dx_ = p_.x - qx;                                           \
            float dy_ = p_.y - qy;                                           \
            float d2_ = fmaf(dx_, dx_, dy_ * dy_);                           \
            unsigned long long key_ =                                        \
                (((unsigned long long)__float_as_uint(d2_)) << 32) |         \
                (unsigned)(unsigned short)js[i_];                            \
            if (key_ < k5) {                                                 \
                bool c4 = key_ < k4, c3 = key_ < k3, c2 = key_ < k2,         \
                     c1_ = key_ < k1, c0_ = key_ < k0;                       \
                k5 = c4 ? k4 : key_;                                         \
                k4 = c4 ? (c3 ? k3 : key_) : k4;                             \
                k3 = c3 ? (c2 ? k2 : key_) : k3;                             \
                k2 = c2 ? (c1_ ? k1 : key_) : k2;                            \
                k1 = c1_ ? (c0_ ? k0 : key_) : k1;                           \
                k0 = c0_ ? key_ : k0;                                        \
            }                                                                \
        }                                                                    \
    }

#define CHECK_PROC(ci, cj)                                                   \
    {                                                                        \
        float dxm_ = fmaxf(0.f, fmaxf((ci) * CW - qx, qx - ((ci) + 1) * CW));\
        float dym_ = fmaxf(0.f, fmaxf((cj) * CW - qy, qy - ((cj) + 1) * CW));\
        float bd_ = __uint_as_float((unsigned)(k5 >> 32));                   \
        if (fmaf(dxm_, dxm_, dym_ * dym_) <= bd_) PROC_CELL((cj) * NCX + (ci));\
    }

    int cx = (int)(qx * 16.0f); cx = cx < 0 ? 0 : (cx > 15 ? 15 : cx);
    int cy = (int)(qy * 16.0f); cy = cy < 0 ? 0 : (cy > 15 ? 15 : cy);

    PROC_CELL(cy * NCX + cx);

    for (int r = 1; r < 16; r++) {
        float dmin = (r - 1) * CW;
        float bd5 = __uint_as_float((unsigned)(k5 >> 32));
        if (dmin * dmin > bd5) break;

        int ci0 = cx - r < 0 ? 0 : cx - r;
        int ci1 = cx + r > 15 ? 15 : cx + r;
        if (cy - r >= 0) {
            int cj = cy - r;
            for (int ci = ci0; ci <= ci1; ci++) CHECK_PROC(ci, cj);
        }
        if (cy + r <= 15) {
            int cj = cy + r;
            for (int ci = ci0; ci <= ci1; ci++) CHECK_PROC(ci, cj);
        }
        int cj0 = cy - r + 1 < 0 ? 0 : cy - r + 1;
        int cj1 = cy + r - 1 > 15 ? 15 : cy + r - 1;
        if (cx - r >= 0) {
            int ci = cx - r;
            for (int cj = cj0; cj <= cj1; cj++) CHECK_PROC(ci, cj);
        }
        if (cx + r <= 15) {
            int ci = cx + r;
            for (int cj = cj0; cj <= cj1; cj++) CHECK_PROC(ci, cj);
        }
    }
#undef CHECK_PROC
#undef PROC_CELL

    int obase = (b * NN + n) * KK;
    g_nbr[obase + 0] = (int)(k0 & 0xffffffffu);
    g_nbr[obase + 1] = (int)(k1 & 0xffffffffu);
    g_nbr[obase + 2] = (int)(k2 & 0xffffffffu);
    g_nbr[obase + 3] = (int)(k3 & 0xffffffffu);
    g_nbr[obase + 4] = (int)(k4 & 0xffffffffu);
    g_nbr[obase + 5] = (int)(k5 & 0xffffffffu);
}

// ---------------------------------------------------------------------------
// K2: materialize G[j,k,d] = x_j*P[k,d] + y_j*Q[k,d] + R[k,d].
// grid = 768 blocks x 256 threads; 1 warp per (j,k) row.
// ---------------------------------------------------------------------------
__global__ void k_matG(const float* __restrict__ loc) {
    const int wid = blockIdx.x * 8 + (threadIdx.x >> 5);   // 0..6143 = j*6+k
    const int l = threadIdx.x & 31;
    const int j = wid / KK, k = wid - j * KK;

    float2 pj = __ldg((const float2*)loc + j);             // batch 0
    float4 P = __ldg((const float4*)(g_P + k * DD) + l);
    float4 Q = __ldg((const float4*)(g_Q + k * DD) + l);
    float4 R = __ldg((const float4*)(g_R + k * DD) + l);

    float4 o;
    o.x = fmaf(pj.x, P.x, fmaf(pj.y, Q.x, R.x));
    o.y = fmaf(pj.x, P.y, fmaf(pj.y, Q.y, R.y));
    o.z = fmaf(pj.x, P.z, fmaf(pj.y, Q.z, R.z));
    o.w = fmaf(pj.x, P.w, fmaf(pj.y, Q.w, R.w));
    ((float4*)(g_G + (size_t)wid * DD))[l] = o;
}

// ---------------------------------------------------------------------------
// K3: gather (R10-proven, verbatim): G rows + bnb + F3 + leaky; write h;
// block mean partials. grid = 8192 (8 rows, 1 warp/row), 256 threads.
// ---------------------------------------------------------------------------
__global__ void k_gather(const float* __restrict__ loc,
                         const float* __restrict__ deadline,
                         const float* __restrict__ W3d,
                         const float* __restrict__ b3d,
                         const float* __restrict__ bnb,
                         float* __restrict__ h) {
    __shared__ float red[8][128];
    const int tid = threadIdx.x;
    const int w = tid >> 5, l = tid & 31;
    const int row = blockIdx.x * 8 + w;
    const int b = row >> 10, n = row & 1023;

    float w3[4][3], b3v[4];
#pragma unroll
    for (int q = 0; q < 4; q++) {
        int d = 4 * l + q;
        w3[q][0] = W3d[d * 3 + 0];
        w3[q][1] = W3d[d * 3 + 1];
        w3[q][2] = W3d[d * 3 + 2];
        b3v[q] = b3d[d];
    }
    float4 bnv = ((const float4*)bnb)[l];
    float a[4] = {bnv.x, bnv.y, bnv.z, bnv.w};

    const int* nb = g_nbr + (size_t)row * KK;
#pragma unroll
    for (int k = 0; k < KK; k++) {
        int j = __ldg(nb + k);
        float4 g = ((const float4*)(g_G + (size_t)(j * KK + k) * DD))[l];
        a[0] += g.x; a[1] += g.y; a[2] += g.z; a[3] += g.w;
    }

    float xn = loc[(size_t)row * 2 + 0];
    float yn = loc[(size_t)row * 2 + 1];
    float tn = deadline[row];

    float4 o;
    float* op = (float*)&o;
#pragma unroll
    for (int q = 0; q < 4; q++) {
        float f3 = fmaf(tn, w3[q][2], fmaf(yn, w3[q][1], fmaf(xn, w3[q][0], b3v[q])));
        float v = a[q] + f3;
        op[q] = (v >= 0.f) ? v : 0.01f * v;
    }
    ((float4*)(h + ((size_t)(b * (NN + 1) + n + 1)) * DD))[l] = o;

    ((float4*)red[w])[l] = o;
    __syncthreads();
    if (tid < 128) {
        float s = 0.f;
#pragma unroll
        for (int q = 0; q < 8; q++) s += red[q][tid];
        g_part[(size_t)blockIdx.x * DD + tid] = s;
    }
}

// ---------------------------------------------------------------------------
// K4: depot row + mean combine (R10-proven). grid = 64, 1024 threads.
// ---------------------------------------------------------------------------
__global__ void k_final(const float* __restrict__ depot,
                        const float* __restrict__ Wdep,
                        const float* __restrict__ bdep,
                        float* __restrict__ h,
                        float* __restrict__ mean_out) {
    __shared__ float red[8][128];
    const int b = blockIdx.x;
    const int tid = threadIdx.x;
    const int d = tid & 127, g = tid >> 7;

    float s = 0.f;
    const float* pp = g_part + (size_t)b * 128 * DD;
#pragma unroll
    for (int q = 0; q < 16; q++) s += pp[(size_t)(g * 16 + q) * DD + d];

    if (g == 0) {
        float dep = fmaf(depot[b * 2 + 1], Wdep[d * 2 + 1],
                         fmaf(depot[b * 2 + 0], Wdep[d * 2 + 0], bdep[d]));
        dep = (dep >= 0.f) ? dep : 0.01f * dep;
        h[(size_t)b * (NN + 1) * DD + d] = dep;
        s += dep;
    }
    red[g][d] = s;
    __syncthreads();
    if (g == 0) {
        float t = 0.f;
#pragma unroll
        for (int q = 0; q < 8; q++) t += red[q][d];
        mean_out[b * DD + d] = t / 1025.0f;
    }
}

// ---------------------------------------------------------------------------
extern "C" void kernel_launch(void* const* d_in, const int* in_sizes, int n_in,
                              void* d_out, int out_size) {
    const float* loc      = (const float*)d_in[0];
    const float* deadline = (const float*)d_in[1];
    const float* depot    = (const float*)d_in[2];
    const float* W3d      = (const float*)d_in[3];
    const float* b3d      = (const float*)d_in[4];
    const float* W2d      = (const float*)d_in[5];
    const float* b2d      = (const float*)d_in[6];
    const float* Wnb      = (const float*)d_in[7];
    const float* bnb      = (const float*)d_in[8];
    const float* Wdep     = (const float*)d_in[9];
    const float* bdep     = (const float*)d_in[10];

    float* h = (float*)d_out;
    float* mean_out = h + (size_t)NB * (NN + 1) * DD;

    k_knn_weights<<<KNN_BLOCKS + KK, 256>>>(loc, W2d, b2d, Wnb);
    k_matG<<<NN * KK / 8, 256>>>(loc);
    k_gather<<<NB * NN / 8, 256>>>(loc, deadline, W3d, b3d, bnb, h);
    k_final<<<NB, 1024>>>(depot, Wdep, bdep, h, mean_out);
}

// round 13
// speedup vs baseline: 1.8429x; 1.2274x over previous
#include <cuda_runtime.h>
#include <cstdint>

#define NB 64
#define NN 1024
#define DD 128
#define KK 6
#define NCX 16
#define NCELL 256
#define CW (1.0f / 16.0f)
#define KNN_BLOCKS NB   // 64: one block per batch

// Scratch (device globals: no allocation allowed)
__device__ int   g_nbr[NB * NN * KK];     // 1.5 MB: neighbor indices
__device__ float g_P[KK * DD];
__device__ float g_Q[KK * DD];
__device__ float g_R[KK * DD];
__device__ float g_part[1024 * DD];       // per-gather-block mean partials

// ---------------------------------------------------------------------------
// K1 (fused): blocks [0,64): exact kNN, one batch per block, 1024 threads.
//             blocks [64,70): weight collapse P/Q/R[k,d] (tid<256 active).
// ---------------------------------------------------------------------------
__global__ __launch_bounds__(1024, 1)
void k_knn_weights(const float* __restrict__ loc,
                   const float* __restrict__ W2d,
                   const float* __restrict__ b2d,
                   const float* __restrict__ Wnb) {
    const int tid = threadIdx.x;

    if (blockIdx.x >= KNN_BLOCKS) {
        // ============ weights path: one k per block (validated R12) ========
        __shared__ float w0s[128], w1s[128], bs[128];
        __shared__ float pa[128], qa[128], ra[128];
        const int k = blockIdx.x - KNN_BLOCKS;
        const int d = tid >> 1, half = tid & 1;
        float p = 0.f, q = 0.f, r = 0.f;

        if (tid < 128) {
            w0s[tid] = W2d[tid * 2 + 0];
            w1s[tid] = W2d[tid * 2 + 1];
            bs[tid]  = b2d[tid];
        }
        __syncthreads();

        if (tid < 256) {
            const float* wrow = Wnb + d * (KK * DD) + k * DD + half * 64;
#pragma unroll 8
            for (int i = 0; i < 64; i++) {
                float wv = __ldg(wrow + i);
                int dd = half * 64 + i;
                p = fmaf(w0s[dd], wv, p);
                q = fmaf(w1s[dd], wv, q);
                r = fmaf(bs[dd],  wv, r);
            }
            if (half) { pa[d] = p; qa[d] = q; ra[d] = r; }
        }
        __syncthreads();
        if (tid < 256 && !half) {
            g_P[k * DD + d] = p + pa[d];
            g_Q[k * DD + d] = q + qa[d];
            g_R[k * DD + d] = r + ra[d];
        }
        return;
    }

    // ============ kNN path: one batch per block ============
    __shared__ float2 lx[NN];
    __shared__ float2 ps[NN];
    __shared__ short  js[NN];
    __shared__ unsigned char cellOf[NN];
    __shared__ unsigned short cnt2[NCELL][32];   // [cell][warp] counts -> bases
    __shared__ int cntTot[NCELL];
    __shared__ int cstart[NCELL];

    const int b = blockIdx.x;
    const int w = tid >> 5, l = tid & 31;
    const unsigned lmask = (1u << l) - 1u;

    // Zero per-(cell,warp) histogram: 8192 uint16 = 4096 uint32.
    for (int i = tid; i < NCELL * 32 / 2; i += 1024)
        ((unsigned*)cnt2)[i] = 0u;

    // Load + cell id (1 point per thread).
    const float2* locb = (const float2*)(loc + (size_t)b * NN * 2);
    {
        float2 p = locb[tid];
        lx[tid] = p;
        int cx = (int)(p.x * 16.0f); cx = cx < 0 ? 0 : (cx > 15 ? 15 : cx);
        int cy = (int)(p.y * 16.0f); cy = cy < 0 ? 0 : (cy > 15 ? 15 : cy);
        cellOf[tid] = (unsigned char)(cy * NCX + cx);
    }
    __syncthreads();

    // Per-(cell,warp) histogram, conflict-free: one leader per (c,w) group.
    {
        int c = cellOf[tid];
        unsigned mask = __match_any_sync(0xffffffffu, c);
        if ((mask & lmask) == 0)               // leader = lowest lane of group
            cnt2[c][w] = (unsigned short)__popc(mask);
    }
    __syncthreads();

    // Per-cell prefix over the 32 warps (thread c handles cell c).
    if (tid < NCELL) {
        int run = 0;
#pragma unroll
        for (int ww = 0; ww < 32; ww++) {
            int t = cnt2[tid][ww];
            cnt2[tid][ww] = (unsigned short)run;
            run += t;
        }
        cntTot[tid] = run;
    }
    __syncthreads();

    // Exclusive prefix over 256 cells by warp 0 (8 cells/lane).
    if (tid < 32) {
        int base = tid * 8;
        int c8[8]; int T = 0;
#pragma unroll
        for (int i = 0; i < 8; i++) { c8[i] = cntTot[base + i]; T += c8[i]; }
        int incl = T;
#pragma unroll
        for (int off = 1; off < 32; off <<= 1) {
            int v = __shfl_up_sync(0xffffffffu, incl, off);
            if (tid >= off) incl += v;
        }
        int run = incl - T;
#pragma unroll
        for (int i = 0; i < 8; i++) { cstart[base + i] = run; run += c8[i]; }
    }
    __syncthreads();

    // Deterministic parallel scatter: j-ascending within each cell
    // (warps ascend in j, lanes ascend in j, bases fixed by prefix).
    {
        int c = cellOf[tid];
        unsigned mask = __match_any_sync(0xffffffffu, c);
        int rank = __popc(mask & lmask);
        int pos = cstart[c] + (int)cnt2[c][w] + rank;
        ps[pos] = lx[tid];
        js[pos] = (short)tid;
    }
    __syncthreads();

    // Query from SORTED position tid (spatially coherent warps).
    const float2 qpt = ps[tid];
    const int n = js[tid];
    const float qx = qpt.x, qy = qpt.y;

    const unsigned long long KINIT =
        (((unsigned long long)0x7f800000u) << 32) | 0xffffffffull;
    unsigned long long k0 = KINIT, k1 = KINIT, k2 = KINIT,
                       k3 = KINIT, k4 = KINIT, k5 = KINIT;

#define PROC_CELL(c)                                                         \
    {                                                                        \
        int s_ = cstart[c];                                                  \
        int e_ = s_ + cntTot[c];                                             \
        for (int i_ = s_; i_ < e_; i_++) {                                   \
            float2 p_ = ps[i_];                                              \
            float dx_ = p_.x - qx;                                           \
            float dy_ = p_.y - qy;                                           \
            float d2_ = fmaf(dx_, dx_, dy_ * dy_);                           \
            unsigned long long key_ =                                        \
                (((unsigned long long)__float_as_uint(d2_)) << 32) |         \
                (unsigned)(unsigned short)js[i_];                            \
            if (key_ < k5) {                                                 \
                bool c4 = key_ < k4, c3 = key_ < k3, c2 = key_ < k2,         \
                     c1_ = key_ < k1, c0_ = key_ < k0;                       \
                k5 = c4 ? k4 : key_;                                         \
                k4 = c4 ? (c3 ? k3 : key_) : k4;                             \
                k3 = c3 ? (c2 ? k2 : key_) : k3;                             \
                k2 = c2 ? (c1_ ? k1 : key_) : k2;                            \
                k1 = c1_ ? (c0_ ? k0 : key_) : k1;                           \
                k0 = c0_ ? key_ : k0;                                        \
            }                                                                \
        }                                                                    \
    }

#define CHECK_PROC(ci, cj)                                                   \
    {                                                                        \
        float dxm_ = fmaxf(0.f, fmaxf((ci) * CW - qx, qx - ((ci) + 1) * CW));\
        float dym_ = fmaxf(0.f, fmaxf((cj) * CW - qy, qy - ((cj) + 1) * CW));\
        float bd_ = __uint_as_float((unsigned)(k5 >> 32));                   \
        if (fmaf(dxm_, dxm_, dym_ * dym_) <= bd_) PROC_CELL((cj) * NCX + (ci));\
    }

    int cx = (int)(qx * 16.0f); cx = cx < 0 ? 0 : (cx > 15 ? 15 : cx);
    int cy = (int)(qy * 16.0f); cy = cy < 0 ? 0 : (cy > 15 ? 15 : cy);

    PROC_CELL(cy * NCX + cx);

    for (int r = 1; r < 16; r++) {
        float dmin = (r - 1) * CW;
        float bd5 = __uint_as_float((unsigned)(k5 >> 32));
        if (dmin * dmin > bd5) break;

        int ci0 = cx - r < 0 ? 0 : cx - r;
        int ci1 = cx + r > 15 ? 15 : cx + r;
        if (cy - r >= 0) {
            int cj = cy - r;
            for (int ci = ci0; ci <= ci1; ci++) CHECK_PROC(ci, cj);
        }
        if (cy + r <= 15) {
            int cj = cy + r;
            for (int ci = ci0; ci <= ci1; ci++) CHECK_PROC(ci, cj);
        }
        int cj0 = cy - r + 1 < 0 ? 0 : cy - r + 1;
        int cj1 = cy + r - 1 > 15 ? 15 : cy + r - 1;
        if (cx - r >= 0) {
            int ci = cx - r;
            for (int cj = cj0; cj <= cj1; cj++) CHECK_PROC(ci, cj);
        }
        if (cx + r <= 15) {
            int ci = cx + r;
            for (int cj = cj0; cj <= cj1; cj++) CHECK_PROC(ci, cj);
        }
    }
#undef CHECK_PROC
#undef PROC_CELL

    int obase = (b * NN + n) * KK;
    g_nbr[obase + 0] = (int)(k0 & 0xffffffffu);
    g_nbr[obase + 1] = (int)(k1 & 0xffffffffu);
    g_nbr[obase + 2] = (int)(k2 & 0xffffffffu);
    g_nbr[obase + 3] = (int)(k3 & 0xffffffffu);
    g_nbr[obase + 4] = (int)(k4 & 0xffffffffu);
    g_nbr[obase + 5] = (int)(k5 & 0xffffffffu);
}

// ---------------------------------------------------------------------------
// K2: Fn = C + sum_k (x_jk*P[k] + y_jk*Q[k]);  + F3 + leaky; write h;
// block mean partials. grid = 1024 x 256; warp handles 8 rows.
// ---------------------------------------------------------------------------
__global__ __launch_bounds__(256)
void k_gather(const float* __restrict__ loc,
              const float* __restrict__ deadline,
              const float* __restrict__ W3d,
              const float* __restrict__ b3d,
              const float* __restrict__ bnb,
              float* __restrict__ h) {
    __shared__ float2 loc0[NN];
    __shared__ float red[8][128];
    const int tid = threadIdx.x;
    const int w = tid >> 5, l = tid & 31;

    // Stage batch-0 coords (feature table domain: nb = F2[0][neighbors]).
    for (int i = tid; i < NN; i += 256) loc0[i] = ((const float2*)loc)[i];

    // Per-thread constants: lane owns d = 4l..4l+3.
    float4 P4[KK], Q4[KK], C4;
    C4 = __ldg((const float4*)bnb + l);
#pragma unroll
    for (int k = 0; k < KK; k++) {
        P4[k] = __ldg((const float4*)(g_P + k * DD) + l);
        Q4[k] = __ldg((const float4*)(g_Q + k * DD) + l);
        float4 r4 = __ldg((const float4*)(g_R + k * DD) + l);
        C4.x += r4.x; C4.y += r4.y; C4.z += r4.z; C4.w += r4.w;
    }
    float w3[4][3], b3v[4];
#pragma unroll
    for (int q = 0; q < 4; q++) {
        int d = 4 * l + q;
        w3[q][0] = __ldg(W3d + d * 3 + 0);
        w3[q][1] = __ldg(W3d + d * 3 + 1);
        w3[q][2] = __ldg(W3d + d * 3 + 2);
        b3v[q] = __ldg(b3d + d);
    }
    __syncthreads();

    float4 macc = {0.f, 0.f, 0.f, 0.f};
    const int row0 = blockIdx.x * 64 + w * 8;   // 16 blocks per batch exactly

#pragma unroll 2
    for (int rr = 0; rr < 8; rr++) {
        const int row = row0 + rr;
        const int b = row >> 10, n = row & 1023;

        const int2* nb2 = (const int2*)(g_nbr + (size_t)row * KK);
        int2 i01 = __ldg(nb2 + 0);
        int2 i23 = __ldg(nb2 + 1);
        int2 i45 = __ldg(nb2 + 2);
        int jid[KK] = {i01.x, i01.y, i23.x, i23.y, i45.x, i45.y};

        float4 a = C4;
#pragma unroll
        for (int k = 0; k < KK; k++) {
            float2 pj = loc0[jid[k]];          // uniform j -> LDS broadcast
            a.x = fmaf(pj.x, P4[k].x, fmaf(pj.y, Q4[k].x, a.x));
            a.y = fmaf(pj.x, P4[k].y, fmaf(pj.y, Q4[k].y, a.y));
            a.z = fmaf(pj.x, P4[k].z, fmaf(pj.y, Q4[k].z, a.z));
            a.w = fmaf(pj.x, P4[k].w, fmaf(pj.y, Q4[k].w, a.w));
        }

        float xn = __ldg(loc + (size_t)row * 2 + 0);
        float yn = __ldg(loc + (size_t)row * 2 + 1);
        float tn = __ldg(deadline + row);

        float4 o;
        float* op = (float*)&o;
        const float* ap = (const float*)&a;
#pragma unroll
        for (int q = 0; q < 4; q++) {
            float f3 = fmaf(tn, w3[q][2], fmaf(yn, w3[q][1], fmaf(xn, w3[q][0], b3v[q])));
            float v = ap[q] + f3;
            op[q] = (v >= 0.f) ? v : 0.01f * v;
        }
        ((float4*)(h + ((size_t)(b * (NN + 1) + n + 1)) * DD))[l] = o;
        macc.x += o.x; macc.y += o.y; macc.z += o.z; macc.w += o.w;
    }

    ((float4*)red[w])[l] = macc;
    __syncthreads();
    if (tid < 128) {
        float s = 0.f;
#pragma unroll
        for (int q = 0; q < 8; q++) s += red[q][tid];
        g_part[(size_t)blockIdx.x * DD + tid] = s;
    }
}

// ---------------------------------------------------------------------------
// K3: depot row + mean combine (16 partials/batch). grid = 64, 256 threads.
// ---------------------------------------------------------------------------
__global__ void k_final(const float* __restrict__ depot,
                        const float* __restrict__ Wdep,
                        const float* __restrict__ bdep,
                        float* __restrict__ h,
                        float* __restrict__ mean_out) {
    __shared__ float red[2][128];
    const int b = blockIdx.x;
    const int tid = threadIdx.x;
    const int d = tid & 127, g = tid >> 7;

    float s = 0.f;
    const float* pp = g_part + (size_t)b * 16 * DD;
#pragma unroll
    for (int q = 0; q < 8; q++) s += pp[(size_t)(g * 8 + q) * DD + d];

    if (g == 0) {
        float dep = fmaf(depot[b * 2 + 1], Wdep[d * 2 + 1],
                         fmaf(depot[b * 2 + 0], Wdep[d * 2 + 0], bdep[d]));
        dep = (dep >= 0.f) ? dep : 0.01f * dep;
        h[(size_t)b * (NN + 1) * DD + d] = dep;
        s += dep;
    }
    red[g][d] = s;
    __syncthreads();
    if (g == 0)
        mean_out[b * DD + d] = (red[0][d] + red[1][d]) / 1025.0f;
}

// ---------------------------------------------------------------------------
extern "C" void kernel_launch(void* const* d_in, const int* in_sizes, int n_in,
                              void* d_out, int out_size) {
    const float* loc      = (const float*)d_in[0];
    const float* deadline = (const float*)d_in[1];
    const float* depot    = (const float*)d_in[2];
    const float* W3d      = (const float*)d_in[3];
    const float* b3d      = (const float*)d_in[4];
    const float* W2d      = (const float*)d_in[5];
    const float* b2d      = (const float*)d_in[6];
    const float* Wnb      = (const float*)d_in[7];
    const float* bnb      = (const float*)d_in[8];
    const float* Wdep     = (const float*)d_in[9];
    const float* bdep     = (const float*)d_in[10];

    float* h = (float*)d_out;
    float* mean_out = h + (size_t)NB * (NN + 1) * DD;

    k_knn_weights<<<KNN_BLOCKS + KK, 1024>>>(loc, W2d, b2d, Wnb);
    k_gather<<<1024, 256>>>(loc, deadline, W3d, b3d, bnb, h);
    k_final<<<NB, 256>>>(depot, Wdep, bdep, h, mean_out);
}

// round 15
// speedup vs baseline: 2.2051x; 1.1966x over previous
#include <cuda_runtime.h>
#include <cstdint>

#define NB 64
#define NN 1024
#define DD 128
#define KK 6
#define NCX 16
#define NCELL 256
#define CW (1.0f / 16.0f)
#define KNN_BLOCKS (NB * 2)   // 128: two blocks per batch, 512 queries each

// Scratch (device globals: no allocation allowed)
__device__ int   g_nbr[NB * NN * KK];     // 1.5 MB: neighbor indices
__device__ float g_P[KK * DD];
__device__ float g_Q[KK * DD];
__device__ float g_R[KK * DD];
__device__ float g_part[1024 * DD];       // per-gather-block mean partials

// ---------------------------------------------------------------------------
// K1 (fused): blocks [0,128): exact kNN, 2 blocks/batch, 512 threads.
//   Both blocks of a batch rebuild the SAME deterministic cell sort, then
//   handle disjoint sorted-position halves (exact partition by construction).
//             blocks [128,134): weight collapse P/Q/R[k,d] (tid<256 active).
// ---------------------------------------------------------------------------
__global__ __launch_bounds__(512, 2)
void k_knn_weights(const float* __restrict__ loc,
                   const float* __restrict__ W2d,
                   const float* __restrict__ b2d,
                   const float* __restrict__ Wnb) {
    const int tid = threadIdx.x;

    if (blockIdx.x >= KNN_BLOCKS) {
        // ============ weights path: one k per block (validated R12) ========
        __shared__ float w0s[128], w1s[128], bs[128];
        __shared__ float pa[128], qa[128], ra[128];
        const int k = blockIdx.x - KNN_BLOCKS;
        const int d = tid >> 1, half = tid & 1;
        float p = 0.f, q = 0.f, r = 0.f;

        if (tid < 128) {
            w0s[tid] = W2d[tid * 2 + 0];
            w1s[tid] = W2d[tid * 2 + 1];
            bs[tid]  = b2d[tid];
        }
        __syncthreads();

        if (tid < 256) {
            const float* wrow = Wnb + d * (KK * DD) + k * DD + half * 64;
#pragma unroll 8
            for (int i = 0; i < 64; i++) {
                float wv = __ldg(wrow + i);
                int dd = half * 64 + i;
                p = fmaf(w0s[dd], wv, p);
                q = fmaf(w1s[dd], wv, q);
                r = fmaf(bs[dd],  wv, r);
            }
            if (half) { pa[d] = p; qa[d] = q; ra[d] = r; }
        }
        __syncthreads();
        if (tid < 256 && !half) {
            g_P[k * DD + d] = p + pa[d];
            g_Q[k * DD + d] = q + qa[d];
            g_R[k * DD + d] = r + ra[d];
        }
        return;
    }

    // ============ kNN path ============
    __shared__ float2 lx[NN];
    __shared__ float2 ps[NN];
    __shared__ short  js[NN];
    __shared__ unsigned char cellOf[NN];
    __shared__ unsigned short cnt2[NCELL][32];   // [cell][j-block of 32] bases
    __shared__ int cntTot[NCELL];
    __shared__ int cstart[NCELL];

    const int b = blockIdx.x >> 1;
    const int halfsel = blockIdx.x & 1;          // which 512 sorted positions
    const int w = tid >> 5, l = tid & 31;
    const unsigned lmask = (1u << l) - 1u;

    // Zero per-(cell,row) histogram: 8192 uint16 = 4096 uint32.
    for (int i = tid; i < NCELL * 32 / 2; i += 512)
        ((unsigned*)cnt2)[i] = 0u;

    // Load 2 points per thread: jA = tid, jB = tid + 512.
    const float2* locb = (const float2*)(loc + (size_t)b * NN * 2);
    int cA, cB;
    {
        float2 p = locb[tid];
        lx[tid] = p;
        int cx = (int)(p.x * 16.0f); cx = cx < 0 ? 0 : (cx > 15 ? 15 : cx);
        int cy = (int)(p.y * 16.0f); cy = cy < 0 ? 0 : (cy > 15 ? 15 : cy);
        cA = cy * NCX + cx;
        cellOf[tid] = (unsigned char)cA;

        p = locb[tid + 512];
        lx[tid + 512] = p;
        cx = (int)(p.x * 16.0f); cx = cx < 0 ? 0 : (cx > 15 ? 15 : cx);
        cy = (int)(p.y * 16.0f); cy = cy < 0 ? 0 : (cy > 15 ? 15 : cy);
        cB = cy * NCX + cx;
        cellOf[tid + 512] = (unsigned char)cB;
    }
    __syncthreads();

    // Per-(cell, j-block) histogram, conflict-free via match leaders.
    // Rows 0..15 = j in [0,512) (warp w), rows 16..31 = j in [512,1024).
    {
        unsigned mask = __match_any_sync(0xffffffffu, cA);
        if ((mask & lmask) == 0) cnt2[cA][w] = (unsigned short)__popc(mask);
        mask = __match_any_sync(0xffffffffu, cB);
        if ((mask & lmask) == 0) cnt2[cB][16 + w] = (unsigned short)__popc(mask);
    }
    __syncthreads();

    // Per-cell prefix over the 32 j-blocks (thread c handles cell c).
    if (tid < NCELL) {
        int run = 0;
#pragma unroll
        for (int ww = 0; ww < 32; ww++) {
            int t = cnt2[tid][ww];
            cnt2[tid][ww] = (unsigned short)run;
            run += t;
        }
        cntTot[tid] = run;
    }
    __syncthreads();

    // Exclusive prefix over 256 cells by warp 0 (8 cells/lane).
    if (tid < 32) {
        int base = tid * 8;
        int c8[8]; int T = 0;
#pragma unroll
        for (int i = 0; i < 8; i++) { c8[i] = cntTot[base + i]; T += c8[i]; }
        int incl = T;
#pragma unroll
        for (int off = 1; off < 32; off <<= 1) {
            int v = __shfl_up_sync(0xffffffffu, incl, off);
            if (tid >= off) incl += v;
        }
        int run = incl - T;
#pragma unroll
        for (int i = 0; i < 8; i++) { cstart[base + i] = run; run += c8[i]; }
    }
    __syncthreads();

    // Deterministic parallel scatter, j-ascending within each cell.
    {
        unsigned mask = __match_any_sync(0xffffffffu, cA);
        int rank = __popc(mask & lmask);
        int pos = cstart[cA] + (int)cnt2[cA][w] + rank;
        ps[pos] = lx[tid];
        js[pos] = (short)tid;

        mask = __match_any_sync(0xffffffffu, cB);
        rank = __popc(mask & lmask);
        pos = cstart[cB] + (int)cnt2[cB][16 + w] + rank;
        ps[pos] = lx[tid + 512];
        js[pos] = (short)(tid + 512);
    }
    __syncthreads();

    // Query from SORTED position halfsel*512 + tid (coherent warps).
    const int sp = halfsel * 512 + tid;
    const float2 qpt = ps[sp];
    const int n = js[sp];
    const float qx = qpt.x, qy = qpt.y;

    const unsigned long long KINIT =
        (((unsigned long long)0x7f800000u) << 32) | 0xffffffffull;
    unsigned long long k0 = KINIT, k1 = KINIT, k2 = KINIT,
                       k3 = KINIT, k4 = KINIT, k5 = KINIT;
    unsigned bd5u = 0x7f800000u;   // hi32(k5), kept in sync after inserts

#define PROC_CELL(c)                                                         \
    {                                                                        \
        int s_ = cstart[c];                                                  \
        int e_ = s_ + cntTot[c];                                             \
        for (int i_ = s_; i_ < e_; i_++) {                                   \
            float2 p_ = ps[i_];                                              \
            float dx_ = p_.x - qx;                                           \
            float dy_ = p_.y - qy;                                           \
            float d2_ = fmaf(dx_, dx_, dy_ * dy_);                           \
            unsigned d2u_ = __float_as_uint(d2_);                            \
            if (d2u_ <= bd5u) {       /* 32-bit fast reject (exact) */       \
                unsigned long long key_ =                                    \
                    (((unsigned long long)d2u_) << 32) |                     \
                    (unsigned)(unsigned short)js[i_];                        \
                if (key_ < k5) {                                             \
                    bool c4 = key_ < k4, c3 = key_ < k3, c2 = key_ < k2,     \
                         c1_ = key_ < k1, c0_ = key_ < k0;                   \
                    k5 = c4 ? k4 : key_;                                     \
                    k4 = c4 ? (c3 ? k3 : key_) : k4;                         \
                    k3 = c3 ? (c2 ? k2 : key_) : k3;                         \
                    k2 = c2 ? (c1_ ? k1 : key_) : k2;                        \
                    k1 = c1_ ? (c0_ ? k0 : key_) : k1;                       \
                    k0 = c0_ ? key_ : k0;                                    \
                    bd5u = (unsigned)(k5 >> 32);                             \
                }                                                            \
            }                                                                \
        }                                                                    \
    }

#define CHECK_PROC(ci, cj)                                                   \
    {                                                                        \
        float dxm_ = fmaxf(0.f, fmaxf((ci) * CW - qx, qx - ((ci) + 1) * CW));\
        float dym_ = fmaxf(0.f, fmaxf((cj) * CW - qy, qy - ((cj) + 1) * CW));\
        float bd_ = __uint_as_float(bd5u);                                   \
        if (fmaf(dxm_, dxm_, dym_ * dym_) <= bd_) PROC_CELL((cj) * NCX + (ci));\
    }

    int cx = (int)(qx * 16.0f); cx = cx < 0 ? 0 : (cx > 15 ? 15 : cx);
    int cy = (int)(qy * 16.0f); cy = cy < 0 ? 0 : (cy > 15 ? 15 : cy);

    PROC_CELL(cy * NCX + cx);

    for (int r = 1; r < 16; r++) {
        float dmin = (r - 1) * CW;
        float bd5 = __uint_as_float(bd5u);
        if (dmin * dmin > bd5) break;

        int ci0 = cx - r < 0 ? 0 : cx - r;
        int ci1 = cx + r > 15 ? 15 : cx + r;
        if (cy - r >= 0) {
            int cj = cy - r;
            for (int ci = ci0; ci <= ci1; ci++) CHECK_PROC(ci, cj);
        }
        if (cy + r <= 15) {
            int cj = cy + r;
            for (int ci = ci0; ci <= ci1; ci++) CHECK_PROC(ci, cj);
        }
        int cj0 = cy - r + 1 < 0 ? 0 : cy - r + 1;
        int cj1 = cy + r - 1 > 15 ? 15 : cy + r - 1;
        if (cx - r >= 0) {
            int ci = cx - r;
            for (int cj = cj0; cj <= cj1; cj++) CHECK_PROC(ci, cj);
        }
        if (cx + r <= 15) {
            int ci = cx + r;
            for (int cj = cj0; cj <= cj1; cj++) CHECK_PROC(ci, cj);
        }
    }
#undef CHECK_PROC
#undef PROC_CELL

    int obase = (b * NN + n) * KK;
    g_nbr[obase + 0] = (int)(k0 & 0xffffffffu);
    g_nbr[obase + 1] = (int)(k1 & 0xffffffffu);
    g_nbr[obase + 2] = (int)(k2 & 0xffffffffu);
    g_nbr[obase + 3] = (int)(k3 & 0xffffffffu);
    g_nbr[obase + 4] = (int)(k4 & 0xffffffffu);
    g_nbr[obase + 5] = (int)(k5 & 0xffffffffu);
}

// ---------------------------------------------------------------------------
// K2: Fn = C + sum_k (x_jk*P[k] + y_jk*Q[k]);  + F3 + leaky; write h;
// block mean partials. grid = 1024 x 256; warp handles 8 rows.
// ---------------------------------------------------------------------------
__global__ __launch_bounds__(256)
void k_gather(const float* __restrict__ loc,
              const float* __restrict__ deadline,
              const float* __restrict__ W3d,
              const float* __restrict__ b3d,
              const float* __restrict__ bnb,
              float* __restrict__ h) {
    __shared__ float2 loc0[NN];
    __shared__ float red[8][128];
    const int tid = threadIdx.x;
    const int w = tid >> 5, l = tid & 31;

    for (int i = tid; i < NN; i += 256) loc0[i] = ((const float2*)loc)[i];

    float4 P4[KK], Q4[KK], C4;
    C4 = __ldg((const float4*)bnb + l);
#pragma unroll
    for (int k = 0; k < KK; k++) {
        P4[k] = __ldg((const float4*)(g_P + k * DD) + l);
        Q4[k] = __ldg((const float4*)(g_Q + k * DD) + l);
        float4 r4 = __ldg((const float4*)(g_R + k * DD) + l);
        C4.x += r4.x; C4.y += r4.y; C4.z += r4.z; C4.w += r4.w;
    }
    float w3[4][3], b3v[4];
#pragma unroll
    for (int q = 0; q < 4; q++) {
        int d = 4 * l + q;
        w3[q][0] = __ldg(W3d + d * 3 + 0);
        w3[q][1] = __ldg(W3d + d * 3 + 1);
        w3[q][2] = __ldg(W3d + d * 3 + 2);
        b3v[q] = __ldg(b3d + d);
    }
    __syncthreads();

    float4 macc = {0.f, 0.f, 0.f, 0.f};
    const int row0 = blockIdx.x * 64 + w * 8;

#pragma unroll 2
    for (int rr = 0; rr < 8; rr++) {
        const int row = row0 + rr;
        const int b = row >> 10, n = row & 1023;

        const int2* nb2 = (const int2*)(g_nbr + (size_t)row * KK);
        int2 i01 = __ldg(nb2 + 0);
        int2 i23 = __ldg(nb2 + 1);
        int2 i45 = __ldg(nb2 + 2);
        int jid[KK] = {i01.x, i01.y, i23.x, i23.y, i45.x, i45.y};

        float4 a = C4;
#pragma unroll
        for (int k = 0; k < KK; k++) {
            float2 pj = loc0[jid[k]];
            a.x = fmaf(pj.x, P4[k].x, fmaf(pj.y, Q4[k].x, a.x));
            a.y = fmaf(pj.x, P4[k].y, fmaf(pj.y, Q4[k].y, a.y));
            a.z = fmaf(pj.x, P4[k].z, fmaf(pj.y, Q4[k].z, a.z));
            a.w = fmaf(pj.x, P4[k].w, fmaf(pj.y, Q4[k].w, a.w));
        }

        float xn = __ldg(loc + (size_t)row * 2 + 0);
        float yn = __ldg(loc + (size_t)row * 2 + 1);
        float tn = __ldg(deadline + row);

        float4 o;
        float* op = (float*)&o;
        const float* ap = (const float*)&a;
#pragma unroll
        for (int q = 0; q < 4; q++) {
            float f3 = fmaf(tn, w3[q][2], fmaf(yn, w3[q][1], fmaf(xn, w3[q][0], b3v[q])));
            float v = ap[q] + f3;
            op[q] = (v >= 0.f) ? v : 0.01f * v;
        }
        ((float4*)(h + ((size_t)(b * (NN + 1) + n + 1)) * DD))[l] = o;
        macc.x += o.x; macc.y += o.y; macc.z += o.z; macc.w += o.w;
    }

    ((float4*)red[w])[l] = macc;
    __syncthreads();
    if (tid < 128) {
        float s = 0.f;
#pragma unroll
        for (int q = 0; q < 8; q++) s += red[q][tid];
        g_part[(size_t)blockIdx.x * DD + tid] = s;
    }
}

// ---------------------------------------------------------------------------
// K3: depot row + mean combine (16 partials/batch). grid = 64, 256 threads.
// ---------------------------------------------------------------------------
__global__ void k_final(const float* __restrict__ depot,
                        const float* __restrict__ Wdep,
                        const float* __restrict__ bdep,
                        float* __restrict__ h,
                        float* __restrict__ mean_out) {
    __shared__ float red[2][128];
    const int b = blockIdx.x;
    const int tid = threadIdx.x;
    const int d = tid & 127, g = tid >> 7;

    float s = 0.f;
    const float* pp = g_part + (size_t)b * 16 * DD;
#pragma unroll
    for (int q = 0; q < 8; q++) s += pp[(size_t)(g * 8 + q) * DD + d];

    if (g == 0) {
        float dep = fmaf(depot[b * 2 + 1], Wdep[d * 2 + 1],
                         fmaf(depot[b * 2 + 0], Wdep[d * 2 + 0], bdep[d]));
        dep = (dep >= 0.f) ? dep : 0.01f * dep;
        h[(size_t)b * (NN + 1) * DD + d] = dep;
        s += dep;
    }
    red[g][d] = s;
    __syncthreads();
    if (g == 0)
        mean_out[b * DD + d] = (red[0][d] + red[1][d]) / 1025.0f;
}

// ---------------------------------------------------------------------------
extern "C" void kernel_launch(void* const* d_in, const int* in_sizes, int n_in,
                              void* d_out, int out_size) {
    const float* loc      = (const float*)d_in[0];
    const float* deadline = (const float*)d_in[1];
    const float* depot    = (const float*)d_in[2];
    const float* W3d      = (const float*)d_in[3];
    const float* b3d      = (const float*)d_in[4];
    const float* W2d      = (const float*)d_in[5];
    const float* b2d      = (const float*)d_in[6];
    const float* Wnb      = (const float*)d_in[7];
    const float* bnb      = (const float*)d_in[8];
    const float* Wdep     = (const float*)d_in[9];
    const float* bdep     = (const float*)d_in[10];

    float* h = (float*)d_out;
    float* mean_out = h + (size_t)NB * (NN + 1) * DD;

    k_knn_weights<<<KNN_BLOCKS + KK, 512>>>(loc, W2d, b2d, Wnb);
    k_gather<<<1024, 256>>>(loc, deadline, W3d, b3d, bnb, h);
    k_final<<<NB, 256>>>(depot, Wdep, bdep, h, mean_out);
}